// round 5
// baseline (speedup 1.0000x reference)
#include <cuda_runtime.h>
#include <math_constants.h>

// Sparsemax along last dim. Input: (64, 1024, 512) fp32 -> 65536 rows x 512.
// One warp per row, 16 fp32/lane in registers (4x float4).
// tau >= max-1 => only elements x > max-1 are candidates (~6/row gaussian).
// Ballot-compact them into a 32-entry per-warp shared buffer (no atomics),
// then Newton on f(tau)=sum(relu(x-tau))-1 from tau0=max-1 (monotone, exact
// on piecewise-linear f). sm_103: integer redux.sync only -> warp max via
// monotone uint key; float sums via shuffle butterfly; counts via ballot.

#define N_COLS 512
#define WARPS_PER_BLOCK 8

// monotone mapping float -> uint (order preserving)
__device__ __forceinline__ unsigned fkey(float x) {
    unsigned b = __float_as_uint(x);
    return b ^ (unsigned)(((int)b >> 31) | 0x80000000);
}
__device__ __forceinline__ float funkey(unsigned k) {
    unsigned m = (unsigned)((~((int)k >> 31)) | 0x80000000);
    return __uint_as_float(k ^ m);
}

__device__ __forceinline__ float warp_sum_f32(float v) {
    #pragma unroll
    for (int o = 16; o; o >>= 1)
        v += __shfl_xor_sync(0xffffffffu, v, o);
    return v;
}

__global__ __launch_bounds__(256) void sparsemax_kernel(
    const float* __restrict__ x, float* __restrict__ out, int rows)
{
    __shared__ float cand[WARPS_PER_BLOCK][32];

    const int wib  = threadIdx.x >> 5;
    const int row  = blockIdx.x * WARPS_PER_BLOCK + wib;
    if (row >= rows) return;
    const int lane = threadIdx.x & 31;
    const unsigned lt_mask = (1u << lane) - 1u;

    const float4* __restrict__ in = reinterpret_cast<const float4*>(x   + (size_t)row * N_COLS);
    float4*       __restrict__ op = reinterpret_cast<float4*>(      out + (size_t)row * N_COLS);

    float z[16];
    unsigned km = 0;
    #pragma unroll
    for (int i = 0; i < 4; i++) {
        float4 v = in[i * 32 + lane];
        z[i*4+0] = v.x; z[i*4+1] = v.y; z[i*4+2] = v.z; z[i*4+3] = v.w;
        float mm = fmaxf(fmaxf(v.x, v.y), fmaxf(v.z, v.w));
        unsigned k = fkey(mm);
        km = k > km ? k : km;
    }
    km = __reduce_max_sync(0xffffffffu, km);     // single-instr warp max
    const float m   = funkey(km);
    const float thr = m - 1.0f;                  // tau >= thr always

    // Ballot-based compaction of candidates (z > thr) into shared (cap 32).
    // Also accumulate s0 = sum(z - thr) for a free first Newton step.
    float s0 = 0.0f;
    int cnt = 0;
    #pragma unroll
    for (int i = 0; i < 16; i++) {
        bool p = z[i] > thr;
        unsigned b = __ballot_sync(0xffffffffu, p);
        if (p) {
            s0 += z[i] - thr;
            int pos = cnt + __popc(b & lt_mask);
            if (pos < 32) cand[wib][pos] = z[i];
        }
        cnt += __popc(b);
    }
    s0 = warp_sum_f32(s0);                       // s0 >= 1 (max contributes 1)
    __syncwarp();                                // make STS visible to LDS

    // First Newton update: tau1 = thr + (s0-1)/cnt (monotone from below)
    float tau = thr + __fdividef(s0 - 1.0f, (float)cnt);

    if (cnt <= 32) {
        // one candidate per lane
        float c = (lane < cnt) ? cand[wib][lane] : -CUDART_INF_F;
        #pragma unroll 1
        for (int it = 0; it < 32; it++) {
            float t = c - tau;
            unsigned b = __ballot_sync(0xffffffffu, t > 0.0f);
            float s = warp_sum_f32(fmaxf(t, 0.0f));
            int   k = __popc(b);
            if (k == 0) break;
            float tn = tau + __fdividef(s - 1.0f, (float)k);
            if (!(tn > tau)) break;              // converged
            tau = tn;
        }
    } else {
        // degenerate rows (many near-max values): scan registers directly
        #pragma unroll 1
        for (int it = 0; it < 64; it++) {
            float s = 0.0f; int k = 0;
            #pragma unroll
            for (int i = 0; i < 16; i++) {
                float t = z[i] - tau;
                if (t > 0.0f) { s += t; k++; }
            }
            s = warp_sum_f32(s);
            k = __reduce_add_sync(0xffffffffu, k);
            if (k == 0) break;
            float tn = tau + __fdividef(s - 1.0f, (float)k);
            if (!(tn > tau)) break;
            tau = tn;
        }
    }

    #pragma unroll
    for (int i = 0; i < 4; i++) {
        float4 v;
        v.x = fmaxf(z[i*4+0] - tau, 0.0f);
        v.y = fmaxf(z[i*4+1] - tau, 0.0f);
        v.z = fmaxf(z[i*4+2] - tau, 0.0f);
        v.w = fmaxf(z[i*4+3] - tau, 0.0f);
        __stcs(&op[i * 32 + lane], v);
    }
}

extern "C" void kernel_launch(void* const* d_in, const int* in_sizes, int n_in,
                              void* d_out, int out_size)
{
    const float* x = (const float*)d_in[0];
    float* out = (float*)d_out;
    const int n = in_sizes[0];
    const int rows = n / N_COLS;

    const int threads = 32 * WARPS_PER_BLOCK;
    const int blocks = (rows + WARPS_PER_BLOCK - 1) / WARPS_PER_BLOCK;
    sparsemax_kernel<<<blocks, threads>>>(x, out, rows);
}

// round 6
// speedup vs baseline: 1.0028x; 1.0028x over previous
#include <cuda_runtime.h>
#include <math_constants.h>

// Sparsemax along last dim. Input: (64, 1024, 512) fp32 -> 65536 rows x 512.
// One warp per row, 16 fp32/lane (4x float4).
// tau >= max-1 => candidates are x > max-1 (~6/row gaussian). Ballot-compact
// into 32-entry per-warp shared buffer; Newton on f(tau)=sum(relu(x-tau))-1
// from tau0=max-1 (monotone from below, exact on piecewise-linear f).
// sm_103 has integer redux.sync only: warp max via monotone uint key;
// Newton (sum,count) packed into ONE u32 redux using t in (0,1]:
//   packed = (k << 26) | round(t * 2^20);  sum-field <= 2^25, no carry.

#define N_COLS 512
#define WARPS_PER_BLOCK 8
#define QSCALE 1048576.0f          // 2^20
#define QINV   (1.0f/1048576.0f)

__device__ __forceinline__ unsigned fkey(float x) {
    unsigned b = __float_as_uint(x);
    return b ^ (unsigned)(((int)b >> 31) | 0x80000000);
}
__device__ __forceinline__ float funkey(unsigned k) {
    unsigned m = (unsigned)((~((int)k >> 31)) | 0x80000000);
    return __uint_as_float(k ^ m);
}

__global__ __launch_bounds__(256) void sparsemax_kernel(
    const float* __restrict__ x, float* __restrict__ out, int rows)
{
    __shared__ float cand[WARPS_PER_BLOCK][32];

    const int wib  = threadIdx.x >> 5;
    const int row  = blockIdx.x * WARPS_PER_BLOCK + wib;
    if (row >= rows) return;
    const int lane = threadIdx.x & 31;
    const unsigned lt_mask = (1u << lane) - 1u;

    const float4* __restrict__ in = reinterpret_cast<const float4*>(x   + (size_t)row * N_COLS);
    float4*       __restrict__ op = reinterpret_cast<float4*>(      out + (size_t)row * N_COLS);

    float z[16];
    float ml = -CUDART_INF_F;
    #pragma unroll
    for (int i = 0; i < 4; i++) {
        float4 v = in[i * 32 + lane];
        z[i*4+0] = v.x; z[i*4+1] = v.y; z[i*4+2] = v.z; z[i*4+3] = v.w;
        ml = fmaxf(ml, fmaxf(fmaxf(v.x, v.y), fmaxf(v.z, v.w)));
    }
    const float m   = funkey(__reduce_max_sync(0xffffffffu, fkey(ml)));
    const float thr = m - 1.0f;                  // tau >= thr always

    // Ballot-compact candidates (z > thr) into shared (cap 32); accumulate
    // s0 = sum(z - thr) locally for a free first Newton step.
    float s0l = 0.0f;
    int cnt = 0;
    #pragma unroll
    for (int i = 0; i < 16; i++) {
        bool p = z[i] > thr;
        unsigned b = __ballot_sync(0xffffffffu, p);
        if (p) {
            s0l += z[i] - thr;
            int pos = cnt + __popc(b & lt_mask);
            if (pos < 32) cand[wib][pos] = z[i];
        }
        cnt += __popc(b);
    }
    // s0l <= 16 per lane -> <= 2^24 quantized; warp sum <= 2^29. One redux.
    unsigned s0i = __reduce_add_sync(0xffffffffu,
                                     __float2uint_rn(s0l * QSCALE));
    float s0 = (float)s0i * QINV;                // s0 >= 1 (max contributes 1)
    __syncwarp();                                // STS -> LDS visibility

    // First Newton update: tau1 = thr + (s0-1)/cnt (monotone from below)
    float tau = thr + __fdividef(s0 - 1.0f, (float)cnt);

    if (cnt <= 32) {
        // one candidate per lane; t = c - tau in (0,1] when positive
        float c = (lane < cnt) ? cand[wib][lane] : -CUDART_INF_F;
        #pragma unroll 1
        for (int it = 0; it < 32; it++) {
            float t = c - tau;
            bool  p = t > 0.0f;
            float tc = p ? t : 0.0f;
            unsigned packed = (p ? (1u << 26) : 0u)
                            + __float2uint_rn(tc * QSCALE);
            unsigned r = __reduce_add_sync(0xffffffffu, packed);
            unsigned k = r >> 26;
            if (k == 0) break;
            float s  = (float)(r & 0x03ffffffu) * QINV;
            float tn = tau + __fdividef(s - 1.0f, (float)k);
            if (!(tn > tau)) break;              // converged
            tau = tn;
        }
    } else {
        // degenerate rows (many near-max values): rescan registers
        #pragma unroll 1
        for (int it = 0; it < 64; it++) {
            float sl = 0.0f; int kl = 0;
            #pragma unroll
            for (int i = 0; i < 16; i++) {
                float t = z[i] - tau;
                if (t > 0.0f) { sl += t; kl++; }
            }
            unsigned si = __reduce_add_sync(0xffffffffu,
                                            __float2uint_rn(sl * QSCALE));
            int k = __reduce_add_sync(0xffffffffu, (unsigned)kl);
            if (k == 0) break;
            float s  = (float)si * QINV;
            float tn = tau + __fdividef(s - 1.0f, (float)k);
            if (!(tn > tau)) break;
            tau = tn;
        }
    }

    #pragma unroll
    for (int i = 0; i < 4; i++) {
        float4 v;
        v.x = fmaxf(z[i*4+0] - tau, 0.0f);
        v.y = fmaxf(z[i*4+1] - tau, 0.0f);
        v.z = fmaxf(z[i*4+2] - tau, 0.0f);
        v.w = fmaxf(z[i*4+3] - tau, 0.0f);
        __stcs(&op[i * 32 + lane], v);
    }
}

extern "C" void kernel_launch(void* const* d_in, const int* in_sizes, int n_in,
                              void* d_out, int out_size)
{
    const float* x = (const float*)d_in[0];
    float* out = (float*)d_out;
    const int n = in_sizes[0];
    const int rows = n / N_COLS;

    const int threads = 32 * WARPS_PER_BLOCK;
    const int blocks = (rows + WARPS_PER_BLOCK - 1) / WARPS_PER_BLOCK;
    sparsemax_kernel<<<blocks, threads>>>(x, out, rows);
}

// round 7
// speedup vs baseline: 1.0056x; 1.0028x over previous
#include <cuda_runtime.h>
#include <math_constants.h>

// Sparsemax along last dim. Input: (64, 1024, 512) fp32 -> 65536 rows x 512.
// One warp per row, 16 fp32/lane (4x float4). tau >= max-1, so only elements
// x > max-1 are support candidates (~6/row gaussian). Each lane keeps its
// last TWO candidates in registers (c0,c1) -- no shared memory, no ballots
// in the hot path. Newton on f(tau)=sum(relu(x-tau))-1 from tau0=max-1
// (monotone from below, exact on piecewise-linear f).
// sm_103: integer redux.sync only. Per Newton iter, (count,sum) packed into
// ONE u32: (k<<26) | round(s * 2^19). Fast path guarantees s<=64, k<=63.

#define N_COLS 512
#define WARPS_PER_BLOCK 8
#define QS   524288.0f             // 2^19
#define QSI  (1.0f/524288.0f)
#define QS20 1048576.0f            // 2^20 (fallback path, separate redux)
#define QSI20 (1.0f/1048576.0f)

__device__ __forceinline__ unsigned fkey(float x) {
    unsigned b = __float_as_uint(x);
    return b ^ (unsigned)(((int)b >> 31) | 0x80000000);
}
__device__ __forceinline__ float funkey(unsigned k) {
    unsigned m = (unsigned)((~((int)k >> 31)) | 0x80000000);
    return __uint_as_float(k ^ m);
}

__global__ __launch_bounds__(256) void sparsemax_kernel(
    const float* __restrict__ x, float* __restrict__ out, int rows)
{
    const int wib  = threadIdx.x >> 5;
    const int row  = blockIdx.x * WARPS_PER_BLOCK + wib;
    if (row >= rows) return;
    const int lane = threadIdx.x & 31;

    const float4* __restrict__ in = reinterpret_cast<const float4*>(x   + (size_t)row * N_COLS);
    float4*       __restrict__ op = reinterpret_cast<float4*>(      out + (size_t)row * N_COLS);

    float z[16];
    float ml = -CUDART_INF_F;
    #pragma unroll
    for (int i = 0; i < 4; i++) {
        float4 v = in[i * 32 + lane];
        z[i*4+0] = v.x; z[i*4+1] = v.y; z[i*4+2] = v.z; z[i*4+3] = v.w;
        ml = fmaxf(ml, fmaxf(fmaxf(v.x, v.y), fmaxf(v.z, v.w)));
    }
    const float m   = funkey(__reduce_max_sync(0xffffffffu, fkey(ml)));
    const float thr = m - 1.0f;                  // tau >= thr always

    // Per-lane candidate collection: keep last two values > thr.
    float c0 = -CUDART_INF_F, c1 = -CUDART_INF_F;
    int nl = 0;
    #pragma unroll
    for (int i = 0; i < 16; i++) {
        if (z[i] > thr) { c1 = c0; c0 = z[i]; nl++; }
    }

    // Gates: overflow (some lane >2 candidates) or exactly-64 candidates
    // (k-field overflow in the packed redux). Both vanishingly rare.
    unsigned bad  = __ballot_sync(0xffffffffu, nl > 2);
    unsigned two  = __ballot_sync(0xffffffffu, nl == 2);
    float tau = thr;

    if (bad == 0u && two != 0xffffffffu) {
        // Fast path: <=2 candidates per lane, cnt <= 63.
        // Newton from tau0 = thr; first iteration doubles as the s0 step.
        #pragma unroll 1
        for (int it = 0; it < 32; it++) {
            float r0 = fmaxf(c0 - tau, 0.0f);
            float r1 = fmaxf(c1 - tau, 0.0f);
            unsigned kk = (r0 > 0.0f) + (r1 > 0.0f);
            unsigned packed = (kk << 26)
                            + __float2uint_rn((r0 + r1) * QS);
            unsigned r = __reduce_add_sync(0xffffffffu, packed);
            unsigned k = r >> 26;
            if (k == 0) break;
            float s  = (float)(r & 0x03ffffffu) * QSI;
            float tn = tau + __fdividef(s - 1.0f, (float)k);
            if (!(tn > tau)) break;              // converged (monotone)
            tau = tn;
        }
    } else {
        // Degenerate rows: rescan registers each iteration.
        #pragma unroll 1
        for (int it = 0; it < 64; it++) {
            float sl = 0.0f; int kl = 0;
            #pragma unroll
            for (int i = 0; i < 16; i++) {
                float t = z[i] - tau;
                if (t > 0.0f) { sl += t; kl++; }
            }
            unsigned si = __reduce_add_sync(0xffffffffu,
                                            __float2uint_rn(sl * QS20));
            int k = __reduce_add_sync(0xffffffffu, (unsigned)kl);
            if (k == 0) break;
            float s  = (float)si * QSI20;
            float tn = tau + __fdividef(s - 1.0f, (float)k);
            if (!(tn > tau)) break;
            tau = tn;
        }
    }

    #pragma unroll
    for (int i = 0; i < 4; i++) {
        float4 v;
        v.x = fmaxf(z[i*4+0] - tau, 0.0f);
        v.y = fmaxf(z[i*4+1] - tau, 0.0f);
        v.z = fmaxf(z[i*4+2] - tau, 0.0f);
        v.w = fmaxf(z[i*4+3] - tau, 0.0f);
        __stcs(&op[i * 32 + lane], v);
    }
}

extern "C" void kernel_launch(void* const* d_in, const int* in_sizes, int n_in,
                              void* d_out, int out_size)
{
    const float* x = (const float*)d_in[0];
    float* out = (float*)d_out;
    const int n = in_sizes[0];
    const int rows = n / N_COLS;

    const int threads = 32 * WARPS_PER_BLOCK;
    const int blocks = (rows + WARPS_PER_BLOCK - 1) / WARPS_PER_BLOCK;
    sparsemax_kernel<<<blocks, threads>>>(x, out, rows);
}